// round 6
// baseline (speedup 1.0000x reference)
#include <cuda_runtime.h>
#include <cstdint>
#include <cfloat>

// Problem shape (fixed by the dataset)
#define B 16
#define Q 20000
#define C 80
#define K 100
#define NCHUNK 16
#define CH (Q / NCHUNK)   // 1250 rows per stage-1 chunk

// Scratch (no cudaMalloc). Fully overwritten every call (deterministic).
__device__ unsigned long long g_cand[B * NCHUNK * K];

// float -> uint monotone map (bigger float => bigger uint)
__device__ __forceinline__ unsigned int f2u(float f) {
    unsigned int u = __float_as_uint(f);
    return (u & 0x80000000u) ? ~u : (u | 0x80000000u);
}

// ---------------------------------------------------------------------------
// Kernel 1 (fused): score + per-chunk exact top-K.
// One block per (batch, chunk of 1250 rows), 1024 threads.
//  Phase A: 4 threads/row, 5 float4 loads each, 2-shuffle max -> smem keys.
//           Shuffles are executed by ALL lanes (loads/writes predicated) to
//           avoid partial-warp __shfl_xor_sync deadlock at the row<CH edge.
//  Phase B: 4-pass MSB radix select (aggregated atomics, parallel suffix scan),
//           gather >= T, bitonic-256 sort of (key|~idx) composites.
// ---------------------------------------------------------------------------
__global__ __launch_bounds__(1024) void score_select_kernel(const float4* __restrict__ lg) {
    const int b  = blockIdx.x >> 4;
    const int ch = blockIdx.x & 15;
    const int tid = threadIdx.x;     // 1024

    __shared__ unsigned int sk[CH];
    __shared__ int hist[256];
    __shared__ int scan[256];
    __shared__ unsigned int s_prefix;
    __shared__ int s_krem;
    __shared__ int s_cnt;
    __shared__ unsigned long long cand[256];

    // ---- Phase A: per-row max ----
    const float4* base = lg + (long long)(b * Q + ch * CH) * 20;
    const int row_local = tid >> 2;
    const int q = tid & 3;

    if (tid == 0) { s_prefix = 0u; s_krem = K; s_cnt = 0; }

    #pragma unroll
    for (int it = 0; it < 5; ++it) {
        int row = it * 256 + row_local;
        bool valid = (row < CH);
        float m = -FLT_MAX;
        if (valid) {
            const float4* p = base + row * 20 + q * 5;
            float4 v0 = p[0], v1 = p[1], v2 = p[2], v3 = p[3], v4 = p[4];
            m = fmaxf(fmaxf(v0.x, v0.y), fmaxf(v0.z, v0.w));
            m = fmaxf(m, fmaxf(fmaxf(v1.x, v1.y), fmaxf(v1.z, v1.w)));
            m = fmaxf(m, fmaxf(fmaxf(v2.x, v2.y), fmaxf(v2.z, v2.w)));
            m = fmaxf(m, fmaxf(fmaxf(v3.x, v3.y), fmaxf(v3.z, v3.w)));
            m = fmaxf(m, fmaxf(fmaxf(v4.x, v4.y), fmaxf(v4.z, v4.w)));
        }
        // all 32 lanes participate (no partial-warp sync)
        m = fmaxf(m, __shfl_xor_sync(0xffffffffu, m, 1));
        m = fmaxf(m, __shfl_xor_sync(0xffffffffu, m, 2));
        if (valid && q == 0) sk[row] = f2u(m);
    }
    __syncthreads();

    // ---- Phase B: exact radix select of 100th-largest ----
    for (int pass = 0; pass < 4; ++pass) {
        int shift = 24 - 8 * pass;
        unsigned int dmask = pass ? (0xFFFFFFFFu << (shift + 8)) : 0u;
        unsigned int prefix = s_prefix;

        if (tid < 256) hist[tid] = 0;
        __syncthreads();

        for (int i = tid; i < CH; i += 1024) {
            unsigned int kk = sk[i];
            if ((kk & dmask) == prefix) {
                unsigned int d = (kk >> shift) & 255u;
                unsigned int mask = __match_any_sync(__activemask(), d);
                int leader = __ffs(mask) - 1;
                if ((tid & 31) == leader) atomicAdd(&hist[d], __popc(mask));
            }
        }
        __syncthreads();

        // parallel suffix sum over 256 bins
        if (tid < 256) scan[tid] = hist[tid];
        __syncthreads();
        #pragma unroll
        for (int off = 1; off < 256; off <<= 1) {
            int v = 0;
            if (tid < 256 && tid + off < 256) v = scan[tid + off];
            __syncthreads();
            if (tid < 256) scan[tid] += v;
            __syncthreads();
        }

        int krem = s_krem;
        __syncthreads();
        if (tid < 256) {
            int nxt = (tid == 255) ? 0 : scan[tid + 1];
            int cur = scan[tid];
            if (cur >= krem && nxt < krem) {   // exactly one thread
                s_prefix = prefix | ((unsigned int)tid << shift);
                s_krem = krem - nxt;
            }
        }
        __syncthreads();
    }

    unsigned int T = s_prefix;  // exact K-th largest key in this chunk

    // gather candidates >= T
    for (int i = tid; i < CH; i += 1024) {
        unsigned int kk = sk[i];
        if (kk >= T) {
            int pos = atomicAdd(&s_cnt, 1);
            if (pos < 256) {
                unsigned int gidx = (unsigned int)(ch * CH + i);  // idx within batch
                cand[pos] = ((unsigned long long)kk << 32) |
                            (unsigned long long)(0xFFFFFFFFu - gidx);
            }
        }
    }
    __syncthreads();
    int n = s_cnt < 256 ? s_cnt : 256;
    if (tid >= n && tid < 256) cand[tid] = 0ull;
    __syncthreads();

    // bitonic sort 256 descending (key desc; ties -> idx asc)
    for (int kk = 2; kk <= 256; kk <<= 1) {
        for (int j = kk >> 1; j > 0; j >>= 1) {
            if (tid < 256) {
                int i = tid, ixj = i ^ j;
                if (ixj > i) {
                    unsigned long long a = cand[i], bb = cand[ixj];
                    bool up = ((i & kk) == 0);
                    if ((a < bb) == up) { cand[i] = bb; cand[ixj] = a; }
                }
            }
            __syncthreads();
        }
    }

    if (tid < K) g_cand[(b * NCHUNK + ch) * K + tid] = cand[tid];
}

// ---------------------------------------------------------------------------
// Kernel 2 (fused): merge 16 sorted top-100 lists -> global top-100, then
// gather boxes + sigmoid(scores) in the same block.
// One block per batch, 1024 threads.
// Output layout: [B*K*4 boxes][B*K*C scores], both f32.
// ---------------------------------------------------------------------------
__global__ __launch_bounds__(1024) void merge_gather_kernel(const float* __restrict__ boxes,
                                                            const float* __restrict__ logits,
                                                            float* __restrict__ out) {
    const int b = blockIdx.x;
    const int tid = threadIdx.x;   // 1024
    __shared__ unsigned long long s[2048];

    const unsigned long long* src = g_cand + b * NCHUNK * K;  // 1600 entries
    s[tid]        = (tid        < NCHUNK * K) ? src[tid]        : 0ull;
    s[tid + 1024] = (tid + 1024 < NCHUNK * K) ? src[tid + 1024] : 0ull;
    __syncthreads();

    // bitonic sort 2048 descending
    for (int kk = 2; kk <= 2048; kk <<= 1) {
        for (int j = kk >> 1; j > 0; j >>= 1) {
            #pragma unroll
            for (int eo = 0; eo < 2048; eo += 1024) {
                int e = tid + eo;
                int p = e ^ j;
                if (p > e) {
                    unsigned long long a = s[e], bb = s[p];
                    bool up = ((e & kk) == 0);
                    if ((a < bb) == up) { s[e] = bb; s[p] = a; }
                }
            }
            __syncthreads();
        }
    }

    // gather: 32 warps cover K=100 detections
    const int w = tid >> 5;
    const int lane = tid & 31;
    for (int j = w; j < K; j += 32) {
        unsigned int enc = (unsigned int)(s[j] & 0xFFFFFFFFull);
        int idx = (int)(0xFFFFFFFFu - enc);

        const float* lrow = logits + ((long long)b * Q + idx) * C;
        float* srow = out + (long long)B * K * 4 + (long long)(b * K + j) * C;

        float x0 = lrow[lane];
        float x1 = lrow[lane + 32];
        srow[lane]      = 1.f / (1.f + __expf(-x0));
        srow[lane + 32] = 1.f / (1.f + __expf(-x1));
        if (lane < 16) {
            float x2 = lrow[lane + 64];
            srow[lane + 64] = 1.f / (1.f + __expf(-x2));
        }
        if (lane < 4) {
            out[(long long)(b * K + j) * 4 + lane] =
                boxes[((long long)b * Q + idx) * 4 + lane];
        }
    }
}

// ---------------------------------------------------------------------------
extern "C" void kernel_launch(void* const* d_in, const int* in_sizes, int n_in,
                              void* d_out, int out_size) {
    const float* boxes  = (const float*)d_in[0];   // (B,Q,4)
    const float* logits = (const float*)d_in[1];   // (B,Q,C)
    float* out = (float*)d_out;

    score_select_kernel<<<B * NCHUNK, 1024>>>((const float4*)logits);
    merge_gather_kernel<<<B, 1024>>>(boxes, logits, out);

    (void)in_sizes; (void)n_in; (void)out_size;
}

// round 7
// speedup vs baseline: 1.3352x; 1.3352x over previous
#include <cuda_runtime.h>
#include <cstdint>
#include <cfloat>

// Problem shape (fixed by the dataset)
#define B 16
#define Q 20000
#define C 80
#define K 100
#define NCHUNK 16
#define CH (Q / NCHUNK)   // 1250 rows per stage-1 chunk

// Scratch (no cudaMalloc). Fully overwritten every call (deterministic).
__device__ unsigned long long g_cand[B * NCHUNK * K];

// float -> uint monotone map (bigger float => bigger uint)
__device__ __forceinline__ unsigned int f2u(float f) {
    unsigned int u = __float_as_uint(f);
    return (u & 0x80000000u) ? ~u : (u | 0x80000000u);
}

__device__ __forceinline__ unsigned long long u64max(unsigned long long a, unsigned long long b) { return a > b ? a : b; }
__device__ __forceinline__ unsigned long long u64min(unsigned long long a, unsigned long long b) { return a < b ? a : b; }

// ---------------------------------------------------------------------------
// Warp-synchronous full bitonic sort, DESCENDING, of 256 u64 elements held as
// 8 registers/lane with element index e = r*32 + lane. No block barriers.
// ---------------------------------------------------------------------------
__device__ __forceinline__ void warp_sort256_desc(unsigned long long c[8], int lane) {
    for (int kk = 2; kk <= 256; kk <<= 1) {
        for (int j = kk >> 1; j >= 1; j >>= 1) {
            if (j >= 32) {                       // partner differs in r only
                int jr = j >> 5;
                #pragma unroll
                for (int rl = 0; rl < 8; ++rl) {
                    if ((rl & jr) == 0) {
                        int rh = rl | jr;
                        bool up = ((rl & (kk >> 5)) == 0);   // kk >= 64 here
                        unsigned long long mx = u64max(c[rl], c[rh]);
                        unsigned long long mn = u64min(c[rl], c[rh]);
                        c[rl] = up ? mx : mn;
                        c[rh] = up ? mn : mx;
                    }
                }
            } else {                              // partner differs in lane
                #pragma unroll
                for (int r = 0; r < 8; ++r) {
                    bool up = (kk >= 32) ? ((r & (kk >> 5)) == 0)
                                         : ((lane & kk) == 0);
                    unsigned long long t = __shfl_xor_sync(0xffffffffu, c[r], j);
                    bool lower = ((lane & j) == 0);
                    c[r] = (lower == up) ? u64max(c[r], t) : u64min(c[r], t);
                }
            }
        }
    }
}

// ---------------------------------------------------------------------------
// Kernel 1 (fused): score + per-chunk exact top-K.
// One block per (batch, chunk of 1250 rows), 1024 threads.
// ---------------------------------------------------------------------------
__global__ __launch_bounds__(1024) void score_select_kernel(const float4* __restrict__ lg) {
    const int b  = blockIdx.x >> 4;
    const int ch = blockIdx.x & 15;
    const int tid = threadIdx.x;     // 1024
    const int w = tid >> 5;
    const int lane = tid & 31;

    __shared__ unsigned int sk[CH];
    __shared__ int hist[256];
    __shared__ unsigned int s_prefix;
    __shared__ int s_krem;
    __shared__ int s_cnt;
    __shared__ unsigned long long cand[256];

    // ---- Phase A: per-row max (4 threads/row, 5 float4 each) ----
    const float4* base = lg + (long long)(b * Q + ch * CH) * 20;
    const int row_local = tid >> 2;
    const int q = tid & 3;

    if (tid == 0) { s_prefix = 0u; s_krem = K; s_cnt = 0; }

    #pragma unroll
    for (int it = 0; it < 5; ++it) {
        int row = it * 256 + row_local;
        bool valid = (row < CH);
        float m = -FLT_MAX;
        if (valid) {
            const float4* p = base + row * 20 + q * 5;
            float4 v0 = p[0], v1 = p[1], v2 = p[2], v3 = p[3], v4 = p[4];
            m = fmaxf(fmaxf(v0.x, v0.y), fmaxf(v0.z, v0.w));
            m = fmaxf(m, fmaxf(fmaxf(v1.x, v1.y), fmaxf(v1.z, v1.w)));
            m = fmaxf(m, fmaxf(fmaxf(v2.x, v2.y), fmaxf(v2.z, v2.w)));
            m = fmaxf(m, fmaxf(fmaxf(v3.x, v3.y), fmaxf(v3.z, v3.w)));
            m = fmaxf(m, fmaxf(fmaxf(v4.x, v4.y), fmaxf(v4.z, v4.w)));
        }
        // all 32 lanes participate (no partial-warp sync)
        m = fmaxf(m, __shfl_xor_sync(0xffffffffu, m, 1));
        m = fmaxf(m, __shfl_xor_sync(0xffffffffu, m, 2));
        if (valid && q == 0) sk[row] = f2u(m);
    }
    __syncthreads();

    // ---- Phase B: exact radix select of 100th-largest (3 barriers/pass) ----
    for (int pass = 0; pass < 4; ++pass) {
        int shift = 24 - 8 * pass;
        unsigned int dmask = pass ? (0xFFFFFFFFu << (shift + 8)) : 0u;
        unsigned int prefix = s_prefix;

        if (tid < 256) hist[tid] = 0;
        __syncthreads();

        for (int i = tid; i < CH; i += 1024) {
            unsigned int kk = sk[i];
            if ((kk & dmask) == prefix) {
                unsigned int d = (kk >> shift) & 255u;
                unsigned int mask = __match_any_sync(__activemask(), d);
                int leader = __ffs(mask) - 1;
                if ((tid & 31) == leader) atomicAdd(&hist[d], __popc(mask));
            }
        }
        __syncthreads();

        // single-warp suffix scan over 256 bins; lane l owns bins [8l, 8l+8)
        if (w == 0) {
            int krem = s_krem;
            int v[8];
            int tot = 0;
            #pragma unroll
            for (int r = 0; r < 8; ++r) { v[r] = hist[lane * 8 + r]; tot += v[r]; }
            // inclusive suffix sum of tot across lanes (run = sum lanes >= lane)
            int run = tot;
            #pragma unroll
            for (int off = 1; off < 32; off <<= 1) {
                int t = __shfl_down_sync(0xffffffffu, run, off);
                if (lane + off < 32) run += t;
            }
            int above = run - tot;           // sum over lanes > lane
            // per-bin suffix within this lane's chunk, from r=7 downward
            int acc = above;
            int sfx[8];
            #pragma unroll
            for (int r = 7; r >= 0; --r) { acc += v[r]; sfx[r] = acc; }
            #pragma unroll
            for (int r = 0; r < 8; ++r) {
                int nxt = (r == 7) ? above : sfx[r + 1];
                if (sfx[r] >= krem && nxt < krem) {    // exactly one (lane,r)
                    s_prefix = prefix | ((unsigned int)(lane * 8 + r) << shift);
                    s_krem = krem - nxt;
                }
            }
        }
        __syncthreads();
    }

    unsigned int T = s_prefix;  // exact K-th largest key in this chunk

    // gather candidates >= T (count in [K, K+dups], capped 256)
    for (int i = tid; i < CH; i += 1024) {
        unsigned int kk = sk[i];
        if (kk >= T) {
            int pos = atomicAdd(&s_cnt, 1);
            if (pos < 256) {
                unsigned int gidx = (unsigned int)(ch * CH + i);  // idx within batch
                cand[pos] = ((unsigned long long)kk << 32) |
                            (unsigned long long)(0xFFFFFFFFu - gidx);
            }
        }
    }
    __syncthreads();
    {
        int n = s_cnt < 256 ? s_cnt : 256;
        if (tid >= n && tid < 256) cand[tid] = 0ull;
    }
    __syncthreads();

    // single-warp register bitonic sort of the 256 candidates, then emit top-K
    if (w == 0) {
        unsigned long long c[8];
        #pragma unroll
        for (int r = 0; r < 8; ++r) c[r] = cand[r * 32 + lane];
        warp_sort256_desc(c, lane);
        unsigned long long* dst = g_cand + (b * NCHUNK + ch) * K;
        #pragma unroll
        for (int r = 0; r < 8; ++r) {
            int e = r * 32 + lane;
            if (e < K) dst[e] = c[r];
        }
    }
}

// ---------------------------------------------------------------------------
// Kernel 2 (fused): tournament-merge 16 sorted top-100 lists (padded to 128)
// via warp-local Batcher merges, then gather boxes + sigmoid(scores).
// One block per batch, 1024 threads. 4 block barriers in the merge.
// Output layout: [B*K*4 boxes][B*K*C scores], both f32.
// ---------------------------------------------------------------------------
__global__ __launch_bounds__(1024) void merge_gather_kernel(const float* __restrict__ boxes,
                                                            const float* __restrict__ logits,
                                                            float* __restrict__ out) {
    const int b = blockIdx.x;
    const int tid = threadIdx.x;   // 1024
    const int w = tid >> 5;
    const int lane = tid & 31;

    // levels (u64 offsets): L0:16 lists @0, L1:8 @2048, L2:4 @3072, L3:2 @3584, L4:1 @3840
    __shared__ unsigned long long buf[3968];

    // load 16 lists of 100, pad each to 128 with 0
    for (int i = tid; i < 16 * 128; i += 1024) {
        int list = i >> 7, pos = i & 127;
        buf[i] = (pos < K) ? g_cand[(b * NCHUNK + list) * K + pos] : 0ull;
    }
    __syncthreads();

    const int srcBase[5] = {0, 2048, 3072, 3584, 3840};
    #pragma unroll
    for (int round = 0; round < 4; ++round) {
        int merges = 8 >> round;    // 8,4,2,1
        if (w < merges) {
            const unsigned long long* A  = buf + srcBase[round] + (2 * w) * 128;
            const unsigned long long* Bp = buf + srcBase[round] + (2 * w + 1) * 128;
            unsigned long long c[4];
            // half-cleaner: c[e] = max(A[e], B[127-e]); result = top-128, bitonic
            #pragma unroll
            for (int r = 0; r < 4; ++r) {
                unsigned long long av = A[r * 32 + lane];
                unsigned long long bv = Bp[(3 - r) * 32 + (31 - lane)];
                c[r] = u64max(av, bv);
            }
            // bitonic merge of bitonic-128, descending
            {   // j = 64 : r ^ 2
                unsigned long long mx, mn;
                mx = u64max(c[0], c[2]); mn = u64min(c[0], c[2]); c[0] = mx; c[2] = mn;
                mx = u64max(c[1], c[3]); mn = u64min(c[1], c[3]); c[1] = mx; c[3] = mn;
            }
            {   // j = 32 : r ^ 1
                unsigned long long mx, mn;
                mx = u64max(c[0], c[1]); mn = u64min(c[0], c[1]); c[0] = mx; c[1] = mn;
                mx = u64max(c[2], c[3]); mn = u64min(c[2], c[3]); c[2] = mx; c[3] = mn;
            }
            #pragma unroll
            for (int j = 16; j >= 1; j >>= 1) {
                #pragma unroll
                for (int r = 0; r < 4; ++r) {
                    unsigned long long t = __shfl_xor_sync(0xffffffffu, c[r], j);
                    bool lower = ((lane & j) == 0);
                    c[r] = lower ? u64max(c[r], t) : u64min(c[r], t);
                }
            }
            unsigned long long* D = buf + srcBase[round + 1] + w * 128;
            #pragma unroll
            for (int r = 0; r < 4; ++r) D[r * 32 + lane] = c[r];
        }
        __syncthreads();
    }

    const unsigned long long* s = buf + 3840;   // global top-128 sorted desc

    // gather: 32 warps cover K=100 detections
    for (int j = w; j < K; j += 32) {
        unsigned int enc = (unsigned int)(s[j] & 0xFFFFFFFFull);
        int idx = (int)(0xFFFFFFFFu - enc);

        const float* lrow = logits + ((long long)b * Q + idx) * C;
        float* srow = out + (long long)B * K * 4 + (long long)(b * K + j) * C;

        float x0 = lrow[lane];
        float x1 = lrow[lane + 32];
        srow[lane]      = 1.f / (1.f + __expf(-x0));
        srow[lane + 32] = 1.f / (1.f + __expf(-x1));
        if (lane < 16) {
            float x2 = lrow[lane + 64];
            srow[lane + 64] = 1.f / (1.f + __expf(-x2));
        }
        if (lane < 4) {
            out[(long long)(b * K + j) * 4 + lane] =
                boxes[((long long)b * Q + idx) * 4 + lane];
        }
    }
}

// ---------------------------------------------------------------------------
extern "C" void kernel_launch(void* const* d_in, const int* in_sizes, int n_in,
                              void* d_out, int out_size) {
    const float* boxes  = (const float*)d_in[0];   // (B,Q,4)
    const float* logits = (const float*)d_in[1];   // (B,Q,C)
    float* out = (float*)d_out;

    score_select_kernel<<<B * NCHUNK, 1024>>>((const float4*)logits);
    merge_gather_kernel<<<B, 1024>>>(boxes, logits, out);

    (void)in_sizes; (void)n_in; (void)out_size;
}

// round 8
// speedup vs baseline: 1.3985x; 1.0475x over previous
#include <cuda_runtime.h>
#include <cstdint>
#include <cfloat>

// Problem shape (fixed by the dataset)
#define B 16
#define Q 20000
#define C 80
#define K 100
#define NCH 8
#define CH 2500            // rows per chunk (Q / NCH)
#define NBLK (B * NCH)     // 128 blocks — all co-resident on 148 SMs

// Scratch (no cudaMalloc). g_cand fully overwritten every call; barrier
// counters always return to 0 before kernel exit (deterministic replays).
__device__ unsigned long long g_cand[B * NCH * K];
__device__ int g_bar1 = 0;
__device__ int g_bar2 = 0;

// float -> uint monotone map (bigger float => bigger uint)
__device__ __forceinline__ unsigned int f2u(float f) {
    unsigned int u = __float_as_uint(f);
    return (u & 0x80000000u) ? ~u : (u | 0x80000000u);
}

__device__ __forceinline__ unsigned long long u64max(unsigned long long a, unsigned long long b) { return a > b ? a : b; }
__device__ __forceinline__ unsigned long long u64min(unsigned long long a, unsigned long long b) { return a < b ? a : b; }

// ---------------------------------------------------------------------------
// Warp-synchronous full bitonic sort, DESCENDING, of 256 u64 elements held as
// 8 registers/lane with element index e = r*32 + lane. No block barriers.
// ---------------------------------------------------------------------------
__device__ __forceinline__ void warp_sort256_desc(unsigned long long c[8], int lane) {
    for (int kk = 2; kk <= 256; kk <<= 1) {
        for (int j = kk >> 1; j >= 1; j >>= 1) {
            if (j >= 32) {                       // partner differs in r only
                int jr = j >> 5;
                #pragma unroll
                for (int rl = 0; rl < 8; ++rl) {
                    if ((rl & jr) == 0) {
                        int rh = rl | jr;
                        bool up = ((rl & (kk >> 5)) == 0);   // kk >= 64 here
                        unsigned long long mx = u64max(c[rl], c[rh]);
                        unsigned long long mn = u64min(c[rl], c[rh]);
                        c[rl] = up ? mx : mn;
                        c[rh] = up ? mn : mx;
                    }
                }
            } else {                              // partner differs in lane
                #pragma unroll
                for (int r = 0; r < 8; ++r) {
                    bool up = (kk >= 32) ? ((r & (kk >> 5)) == 0)
                                         : ((lane & kk) == 0);
                    unsigned long long t = __shfl_xor_sync(0xffffffffu, c[r], j);
                    bool lower = ((lane & j) == 0);
                    c[r] = (lower == up) ? u64max(c[r], t) : u64min(c[r], t);
                }
            }
        }
    }
}

// ---------------------------------------------------------------------------
// Shared memory: phase A/B layout and merger buffer overlap (time-disjoint).
// ---------------------------------------------------------------------------
struct SmemAB {
    unsigned int sk[CH];               // 10000 B
    int hist[256];                     // 1024 B
    unsigned long long cand[256];      // 2048 B
};
union SmemU {
    SmemAB ab;
    unsigned long long mbuf[1920];     // 8x128 @0, 4x128 @1024, 2x128 @1536, 1x128 @1792
};

// ---------------------------------------------------------------------------
// ONE persistent kernel: score -> per-chunk exact top-K -> grid barrier ->
// (blocks 0..15) tournament merge + gather + sigmoid.
// Output layout: [B*K*4 boxes][B*K*C scores], both f32.
// ---------------------------------------------------------------------------
__global__ __launch_bounds__(1024, 1) void fused_all_kernel(const float4* __restrict__ lg,
                                                            const float* __restrict__ boxes,
                                                            const float* __restrict__ logits,
                                                            float* __restrict__ out) {
    const int bid = blockIdx.x;          // 0..127
    const int b   = bid >> 3;            // batch of this scoring chunk
    const int ch  = bid & 7;
    const int tid = threadIdx.x;         // 1024
    const int w = tid >> 5;
    const int lane = tid & 31;

    __shared__ SmemU su;
    __shared__ unsigned int s_prefix;
    __shared__ int s_krem;
    __shared__ int s_cnt;

    // ================= Phase A: per-row max (4 threads/row) =================
    const float4* base = lg + (long long)(b * Q + ch * CH) * 20;
    const int row_local = tid >> 2;
    const int q = tid & 3;

    if (tid == 0) { s_prefix = 0u; s_krem = K; s_cnt = 0; }

    #pragma unroll
    for (int it = 0; it < 10; ++it) {
        int row = it * 256 + row_local;
        bool valid = (row < CH);
        float m = -FLT_MAX;
        if (valid) {
            const float4* p = base + row * 20 + q * 5;
            float4 v0 = p[0], v1 = p[1], v2 = p[2], v3 = p[3], v4 = p[4];
            m = fmaxf(fmaxf(v0.x, v0.y), fmaxf(v0.z, v0.w));
            m = fmaxf(m, fmaxf(fmaxf(v1.x, v1.y), fmaxf(v1.z, v1.w)));
            m = fmaxf(m, fmaxf(fmaxf(v2.x, v2.y), fmaxf(v2.z, v2.w)));
            m = fmaxf(m, fmaxf(fmaxf(v3.x, v3.y), fmaxf(v3.z, v3.w)));
            m = fmaxf(m, fmaxf(fmaxf(v4.x, v4.y), fmaxf(v4.z, v4.w)));
        }
        // all 32 lanes execute the shuffles (no partial-warp sync)
        m = fmaxf(m, __shfl_xor_sync(0xffffffffu, m, 1));
        m = fmaxf(m, __shfl_xor_sync(0xffffffffu, m, 2));
        if (valid && q == 0) su.ab.sk[row] = f2u(m);
    }
    __syncthreads();

    // ============ Phase B: exact radix select of 100th-largest ==============
    for (int pass = 0; pass < 4; ++pass) {
        int shift = 24 - 8 * pass;
        unsigned int dmask = pass ? (0xFFFFFFFFu << (shift + 8)) : 0u;
        unsigned int prefix = s_prefix;

        if (tid < 256) su.ab.hist[tid] = 0;
        __syncthreads();

        for (int i = tid; i < CH; i += 1024) {
            unsigned int kk = su.ab.sk[i];
            if ((kk & dmask) == prefix) {
                unsigned int d = (kk >> shift) & 255u;
                unsigned int mask = __match_any_sync(__activemask(), d);
                int leader = __ffs(mask) - 1;
                if ((tid & 31) == leader) atomicAdd(&su.ab.hist[d], __popc(mask));
            }
        }
        __syncthreads();

        // single-warp suffix scan over 256 bins; lane l owns bins [8l, 8l+8)
        if (w == 0) {
            int krem = s_krem;
            int v[8];
            int tot = 0;
            #pragma unroll
            for (int r = 0; r < 8; ++r) { v[r] = su.ab.hist[lane * 8 + r]; tot += v[r]; }
            int run = tot;
            #pragma unroll
            for (int off = 1; off < 32; off <<= 1) {
                int t = __shfl_down_sync(0xffffffffu, run, off);
                if (lane + off < 32) run += t;
            }
            int above = run - tot;           // sum over lanes > lane
            int acc = above;
            int sfx[8];
            #pragma unroll
            for (int r = 7; r >= 0; --r) { acc += v[r]; sfx[r] = acc; }
            #pragma unroll
            for (int r = 0; r < 8; ++r) {
                int nxt = (r == 7) ? above : sfx[r + 1];
                if (sfx[r] >= krem && nxt < krem) {    // exactly one (lane,r)
                    s_prefix = prefix | ((unsigned int)(lane * 8 + r) << shift);
                    s_krem = krem - nxt;
                }
            }
        }
        __syncthreads();
    }

    unsigned int T = s_prefix;  // exact K-th largest key in this chunk

    for (int i = tid; i < CH; i += 1024) {
        unsigned int kk = su.ab.sk[i];
        if (kk >= T) {
            int pos = atomicAdd(&s_cnt, 1);
            if (pos < 256) {
                unsigned int gidx = (unsigned int)(ch * CH + i);  // idx within batch
                su.ab.cand[pos] = ((unsigned long long)kk << 32) |
                                  (unsigned long long)(0xFFFFFFFFu - gidx);
            }
        }
    }
    __syncthreads();
    {
        int n = s_cnt < 256 ? s_cnt : 256;
        if (tid >= n && tid < 256) su.ab.cand[tid] = 0ull;
    }
    __syncthreads();

    // warp-0 register bitonic sort; emit this chunk's sorted top-K
    if (w == 0) {
        unsigned long long c[8];
        #pragma unroll
        for (int r = 0; r < 8; ++r) c[r] = su.ab.cand[r * 32 + lane];
        warp_sort256_desc(c, lane);
        unsigned long long* dst = g_cand + bid * K;   // bid == b*NCH + ch
        #pragma unroll
        for (int r = 0; r < 8; ++r) {
            int e = r * 32 + lane;
            if (e < K) dst[e] = c[r];
        }
    }

    // ===================== grid barrier (all 128 blocks) ====================
    __threadfence();      // order this block's g_cand stores before arrival
    __syncthreads();
    if (tid == 0) atomicAdd(&g_bar1, 1);

    if (bid >= B) return;   // non-merger blocks done

    if (tid == 0) {
        // bounded spin (safety valve; legit wait is << this)
        long long guard = 0;
        while (*((volatile int*)&g_bar1) < NBLK && guard < (1LL << 31)) ++guard;
        __threadfence();
    }
    __syncthreads();

    // =============== merge 8 sorted lists of batch `bid` ====================
    for (int i = tid; i < 8 * 128; i += 1024) {
        int list = i >> 7, pos = i & 127;
        su.mbuf[i] = (pos < K) ? g_cand[(bid * NCH + list) * K + pos] : 0ull;
    }
    __syncthreads();

    const int srcBase[4] = {0, 1024, 1536, 1792};
    #pragma unroll
    for (int round = 0; round < 3; ++round) {
        int merges = 4 >> round;    // 4,2,1
        if (w < merges) {
            const unsigned long long* A  = su.mbuf + srcBase[round] + (2 * w) * 128;
            const unsigned long long* Bp = su.mbuf + srcBase[round] + (2 * w + 1) * 128;
            unsigned long long c[4];
            // half-cleaner: c[e] = max(A[e], B[127-e]) -> top-128, bitonic
            #pragma unroll
            for (int r = 0; r < 4; ++r) {
                unsigned long long av = A[r * 32 + lane];
                unsigned long long bv = Bp[(3 - r) * 32 + (31 - lane)];
                c[r] = u64max(av, bv);
            }
            {   // j = 64
                unsigned long long mx, mn;
                mx = u64max(c[0], c[2]); mn = u64min(c[0], c[2]); c[0] = mx; c[2] = mn;
                mx = u64max(c[1], c[3]); mn = u64min(c[1], c[3]); c[1] = mx; c[3] = mn;
            }
            {   // j = 32
                unsigned long long mx, mn;
                mx = u64max(c[0], c[1]); mn = u64min(c[0], c[1]); c[0] = mx; c[1] = mn;
                mx = u64max(c[2], c[3]); mn = u64min(c[2], c[3]); c[2] = mx; c[3] = mn;
            }
            #pragma unroll
            for (int j = 16; j >= 1; j >>= 1) {
                #pragma unroll
                for (int r = 0; r < 4; ++r) {
                    unsigned long long t = __shfl_xor_sync(0xffffffffu, c[r], j);
                    bool lower = ((lane & j) == 0);
                    c[r] = lower ? u64max(c[r], t) : u64min(c[r], t);
                }
            }
            unsigned long long* D = su.mbuf + srcBase[round + 1] + w * 128;
            #pragma unroll
            for (int r = 0; r < 4; ++r) D[r * 32 + lane] = c[r];
        }
        __syncthreads();
    }

    const unsigned long long* s = su.mbuf + 1792;   // batch top-128, sorted desc

    // ================== gather + sigmoid (32 warps, K dets) =================
    for (int j = w; j < K; j += 32) {
        unsigned int enc = (unsigned int)(s[j] & 0xFFFFFFFFull);
        int idx = (int)(0xFFFFFFFFu - enc);

        const float* lrow = logits + ((long long)bid * Q + idx) * C;
        float* srow = out + (long long)B * K * 4 + (long long)(bid * K + j) * C;

        float x0 = lrow[lane];
        float x1 = lrow[lane + 32];
        srow[lane]      = 1.f / (1.f + __expf(-x0));
        srow[lane + 32] = 1.f / (1.f + __expf(-x1));
        if (lane < 16) {
            float x2 = lrow[lane + 64];
            srow[lane + 64] = 1.f / (1.f + __expf(-x2));
        }
        if (lane < 4) {
            out[(long long)(bid * K + j) * 4 + lane] =
                boxes[((long long)bid * Q + idx) * 4 + lane];
        }
    }

    // ============ reset barrier counters for the next graph replay ==========
    __syncthreads();
    if (tid == 0) {
        __threadfence();
        if (atomicAdd(&g_bar2, 1) == B - 1) {   // last merger; all passed spin
            atomicExch(&g_bar1, 0);
            atomicExch(&g_bar2, 0);
        }
    }
}

// ---------------------------------------------------------------------------
extern "C" void kernel_launch(void* const* d_in, const int* in_sizes, int n_in,
                              void* d_out, int out_size) {
    const float* boxes  = (const float*)d_in[0];   // (B,Q,4)
    const float* logits = (const float*)d_in[1];   // (B,Q,C)
    float* out = (float*)d_out;

    fused_all_kernel<<<NBLK, 1024>>>((const float4*)logits, boxes, logits, out);

    (void)in_sizes; (void)n_in; (void)out_size;
}